// round 15
// baseline (speedup 1.0000x reference)
#include <cuda_runtime.h>
#include <cuda_fp16.h>
#include <mma.h>
#include <cstdint>

using namespace nvcuda;

#define NTOK 2048
#define DDIM 512
#define HDIM 2048
#define GNUM 4
#define EPG  4
#define ENUM 16
#define GTP_THR 0.9f
#define TP_THR  0.9f
#define SCALE_W 0.5f

// ---------------- scratch ----------------
__device__ float d_tw[NTOK * ENUM];
__device__ int   d_slot[NTOK * ENUM];
__device__ int   d_bucket_tok[ENUM * NTOK];
__device__ float d_bucket_w[ENUM * NTOK];
__device__ int   d_counts[ENUM];
__device__ __half d_h16[(size_t)ENUM * NTOK * HDIM];    // 128 MB
__device__ __half d_w1h[(size_t)ENUM * DDIM * HDIM];    // 32 MB  [e][k=D][n=H]
__device__ __half d_w3h[(size_t)ENUM * DDIM * HDIM];    // 32 MB
__device__ __half d_w2h[(size_t)ENUM * HDIM * DDIM];    // 32 MB  [e][k=H][n=D]
__device__ float d_partial[(size_t)ENUM * NTOK * DDIM]; // 64 MB

// ---------------- helpers ----------------
__device__ __forceinline__ void cvthi4(float4 v, __half* hi) {
    ((__half2*)hi)[0] = __floats2half2_rn(v.x, v.y);
    ((__half2*)hi)[1] = __floats2half2_rn(v.z, v.w);
}

// ---------------- routing ----------------
__device__ __forceinline__ void top2norm(const float* logit, float thr, float* w) {
    float m = logit[0];
    #pragma unroll
    for (int i = 1; i < 4; i++) m = fmaxf(m, logit[i]);
    float p[4], s = 0.f;
    #pragma unroll
    for (int i = 0; i < 4; i++) { p[i] = expf(logit[i] - m); s += p[i]; }
    #pragma unroll
    for (int i = 0; i < 4; i++) p[i] /= s;
    int i0 = 0; float b0 = p[0];
    #pragma unroll
    for (int i = 1; i < 4; i++) if (p[i] > b0) { b0 = p[i]; i0 = i; }
    int i1 = -1; float b1 = -1.f;
    #pragma unroll
    for (int i = 0; i < 4; i++) if (i != i0 && p[i] > b1) { b1 = p[i]; i1 = i; }
    bool act1 = (b0 + b1) <= thr;
    float mp1 = act1 ? b1 : 0.f;
    float den = b0 + mp1 + 1e-9f;
    #pragma unroll
    for (int i = 0; i < 4; i++) w[i] = 0.f;
    w[i0] = b0 / den;
    w[i1] = mp1 / den;
}

__global__ __launch_bounds__(256) void routing_kernel(
    const float* __restrict__ x, const float* __restrict__ Wr,
    const float* __restrict__ br, const float* __restrict__ Wg,
    const float* __restrict__ bg)
{
    int wid = threadIdx.x >> 5, lane = threadIdx.x & 31;
    int n = blockIdx.x * 8 + wid;
    const float* xr = x + (size_t)n * DDIM;
    float xv[16];
    #pragma unroll
    for (int i = 0; i < 16; i++) xv[i] = xr[lane + 32 * i];

    float acc[20];
    #pragma unroll
    for (int g = 0; g < 4; g++) {
        float s = 0.f;
        #pragma unroll
        for (int i = 0; i < 16; i++) s += xv[i] * Wr[(lane + 32 * i) * 4 + g];
        acc[g] = s;
    }
    #pragma unroll
    for (int g = 0; g < 4; g++) {
        #pragma unroll
        for (int e = 0; e < 4; e++) {
            float s = 0.f;
            const float* wgp = Wg + (size_t)g * DDIM * EPG + e;
            #pragma unroll
            for (int i = 0; i < 16; i++) s += xv[i] * wgp[(lane + 32 * i) * 4];
            acc[4 + g * 4 + e] = s;
        }
    }
    #pragma unroll
    for (int o = 16; o; o >>= 1) {
        #pragma unroll
        for (int j = 0; j < 20; j++) acc[j] += __shfl_xor_sync(0xffffffffu, acc[j], o);
    }
    if (lane == 0) {
        float gl[4];
        #pragma unroll
        for (int g = 0; g < 4; g++) gl[g] = acc[g] + br[g];
        float wgrp[4];
        top2norm(gl, GTP_THR, wgrp);
        #pragma unroll
        for (int g = 0; g < 4; g++) {
            float el[4];
            #pragma unroll
            for (int e = 0; e < 4; e++) el[e] = acc[4 + g * 4 + e] + bg[g * 4 + e];
            float wexp[4];
            top2norm(el, TP_THR, wexp);
            #pragma unroll
            for (int e = 0; e < 4; e++) {
                d_tw[n * ENUM + g * 4 + e] = wgrp[g] * wexp[e] * SCALE_W;
                d_slot[n * ENUM + g * 4 + e] = -1;
            }
        }
    }
}

// ---------------- bucket build ----------------
__global__ __launch_bounds__(256) void build_buckets() {
    int e = blockIdx.x;
    int t = threadIdx.x;
    __shared__ int sc[256];
    int base = t * 8;
    float wv[8];
    int flags = 0, cnt = 0;
    #pragma unroll
    for (int j = 0; j < 8; j++) {
        float v = d_tw[(base + j) * ENUM + e];
        wv[j] = v;
        if (v > 0.f) { flags |= 1 << j; cnt++; }
    }
    sc[t] = cnt;
    __syncthreads();
    for (int off = 1; off < 256; off <<= 1) {
        int v = sc[t];
        int add = (t >= off) ? sc[t - off] : 0;
        __syncthreads();
        sc[t] = v + add;
        __syncthreads();
    }
    int pos = sc[t] - cnt;
    #pragma unroll
    for (int j = 0; j < 8; j++) {
        if ((flags >> j) & 1) {
            int n = base + j;
            d_bucket_tok[e * NTOK + pos] = n;
            d_bucket_w[e * NTOK + pos] = wv[j];
            d_slot[n * ENUM + e] = pos;
            pos++;
        }
    }
    if (t == 255) d_counts[e] = sc[255];
}

// ---------------- weight fp32->fp16 (streaming, grid-stride) ----------------
__global__ __launch_bounds__(256) void convw3(
    const float* __restrict__ W1, const float* __restrict__ W3,
    const float* __restrict__ W2)
{
    const size_t N4 = (size_t)ENUM * DDIM * HDIM / 4;  // float4 count per matrix
    size_t stride = (size_t)gridDim.x * 256;
    for (size_t i = blockIdx.x * 256 + threadIdx.x; i < 3 * N4; i += stride) {
        const float* s; __half* d; size_t off;
        if (i < N4)          { s = W1; d = d_w1h; off = i; }
        else if (i < 2 * N4) { s = W3; d = d_w3h; off = i - N4; }
        else                 { s = W2; d = d_w2h; off = i - 2 * N4; }
        float4 v = *(const float4*)(s + off * 4);
        *(__half2*)(d + off * 4)     = __floats2half2_rn(v.x, v.y);
        *(__half2*)(d + off * 4 + 2) = __floats2half2_rn(v.z, v.w);
    }
}

// =============================================================================
// wmma_up: block 128(M) x 128(N) for BOTH u=xW1 and v=xW3. K-chunk 32, 16 chunks.
// 8 warps (2m x 4n), warp tile 64x32-dual. A staged via smem (fp32->fp16 in-
// kernel); B fragments loaded DIRECT from global fp16 weights (no staging).
// Static smem: A double buffer 2x5120 halfs (20KB); epilogue aliases it.
// =============================================================================
__global__ __launch_bounds__(256, 1) void wmma_up(const float* __restrict__ x)
{
    __shared__ __align__(16) __half SMA[2][5120];   // A: 128 rows x 40-stride
    __shared__ __align__(16) float  EPI[8][576];
    int e = blockIdx.z;
    int cnt = d_counts[e];
    if (cnt == 0) return;
    int cntp = (cnt + 127) & ~127;
    int m0 = blockIdx.y * 128;
    if (m0 >= cntp) return;
    int n0 = blockIdx.x * 128;
    int tid = threadIdx.x, lane = tid & 31, wid = tid >> 5;
    const int NK = DDIM / 32;

    int ar = tid >> 1, ap = (tid & 1) * 16;
    int gi = m0 + ar; if (gi > cnt - 1) gi = cnt - 1;
    const float* xrow = x + (size_t)d_bucket_tok[e * NTOK + gi] * DDIM;
    const __half* B1g = d_w1h + (size_t)e * DDIM * HDIM + n0;
    const __half* B3g = d_w3h + (size_t)e * DDIM * HDIM + n0;

    float4 rA[4];
    auto ldreg = [&](int kc) {
        int k0 = kc * 32;
        #pragma unroll
        for (int q = 0; q < 4; q++) rA[q] = *(const float4*)(xrow + k0 + ap + q * 4);
    };
    auto sts = [&](int b) {
        #pragma unroll
        for (int q = 0; q < 4; q++) cvthi4(rA[q], &SMA[b][ar * 40 + ap + q * 4]);
    };

    int wm = wid & 1, wn = wid >> 1;
    wmma::fragment<wmma::accumulator, 16, 16, 16, float> u[4][2], v[4][2];
    #pragma unroll
    for (int i = 0; i < 4; i++)
        #pragma unroll
        for (int j = 0; j < 2; j++) {
            wmma::fill_fragment(u[i][j], 0.0f);
            wmma::fill_fragment(v[i][j], 0.0f);
        }

    ldreg(0);
    for (int kc = 0; kc < NK; kc++) {
        int b = kc & 1;
        sts(b);
        if (kc + 1 < NK) ldreg(kc + 1);
        __syncthreads();
        #pragma unroll
        for (int ks = 0; ks < 2; ks++) {
            int kk = kc * 32 + ks * 16;
            wmma::fragment<wmma::matrix_a, 16, 16, 16, __half, wmma::row_major> fa[4];
            #pragma unroll
            for (int i = 0; i < 4; i++)
                wmma::load_matrix_sync(fa[i], &SMA[b][(wm * 64 + 16 * i) * 40 + ks * 16], 40);
            #pragma unroll
            for (int j = 0; j < 2; j++) {
                wmma::fragment<wmma::matrix_b, 16, 16, 16, __half, wmma::row_major> f1, f3;
                wmma::load_matrix_sync(f1, B1g + (size_t)kk * HDIM + wn * 32 + 16 * j, HDIM);
                wmma::load_matrix_sync(f3, B3g + (size_t)kk * HDIM + wn * 32 + 16 * j, HDIM);
                #pragma unroll
                for (int i = 0; i < 4; i++) {
                    wmma::mma_sync(u[i][j], fa[i], f1, u[i][j]);
                    wmma::mma_sync(v[i][j], fa[i], f3, v[i][j]);
                }
            }
        }
    }
    __syncthreads();

    // epilogue: h = silu(u)*v -> fp16
    float* epi = EPI[wid];
    int r = lane >> 1, c0 = (lane & 1) * 8;
    #pragma unroll
    for (int i = 0; i < 4; i++)
        #pragma unroll
        for (int j = 0; j < 2; j++) {
            #pragma unroll
            for (int t = 0; t < u[i][j].num_elements; t++) {
                float uu = u[i][j].x[t];
                u[i][j].x[t] = uu / (1.f + __expf(-uu)) * v[i][j].x[t];
            }
            wmma::store_matrix_sync(epi, u[i][j], 36, wmma::mem_row_major);
            __syncwarp();
            int grow = m0 + wm * 64 + 16 * i + r;
            int gcol = n0 + wn * 32 + 16 * j + c0;
            __half2* op = (__half2*)(d_h16 + ((size_t)e * NTOK + grow) * HDIM + gcol);
            #pragma unroll
            for (int q = 0; q < 4; q++)
                op[q] = __floats2half2_rn(epi[r * 36 + c0 + 2 * q],
                                          epi[r * 36 + c0 + 2 * q + 1]);
            __syncwarp();
        }
}

// =============================================================================
// wmma_down: block 128(M) x 128(N). Barrier-free mainloop: BOTH operands are
// fp16 in global (d_h16, d_w2h) -> direct fragment loads, no smem staging.
// 8 warps (4m x 2n), warp tile 32x64, single live fb. 2 CTAs/SM.
// =============================================================================
__global__ __launch_bounds__(256, 2) void wmma_down()
{
    __shared__ __align__(16) float EPI[8][576];
    int e = blockIdx.z;
    int cnt = d_counts[e];
    if (cnt == 0) return;
    int cntp = (cnt + 127) & ~127;
    int m0 = blockIdx.y * 128;
    if (m0 >= cntp) return;
    int n0 = blockIdx.x * 128;
    int tid = threadIdx.x, lane = tid & 31, wid = tid >> 5;

    int wm = wid & 3, wn = wid >> 2;
    const __half* Ag = d_h16 + ((size_t)e * NTOK + m0 + wm * 32) * HDIM;
    const __half* Bg = d_w2h + (size_t)e * HDIM * DDIM + n0 + wn * 64;

    wmma::fragment<wmma::accumulator, 16, 16, 16, float> c[2][4];
    #pragma unroll
    for (int i = 0; i < 2; i++)
        #pragma unroll
        for (int j = 0; j < 4; j++) wmma::fill_fragment(c[i][j], 0.0f);

    for (int k = 0; k < HDIM; k += 16) {
        wmma::fragment<wmma::matrix_a, 16, 16, 16, __half, wmma::row_major> fa[2];
        wmma::load_matrix_sync(fa[0], Ag + k, HDIM);
        wmma::load_matrix_sync(fa[1], Ag + 16 * HDIM + k, HDIM);
        #pragma unroll
        for (int j = 0; j < 4; j++) {
            wmma::fragment<wmma::matrix_b, 16, 16, 16, __half, wmma::row_major> fb;
            wmma::load_matrix_sync(fb, Bg + (size_t)k * DDIM + 16 * j, DDIM);
            wmma::mma_sync(c[0][j], fa[0], fb, c[0][j]);
            wmma::mma_sync(c[1][j], fa[1], fb, c[1][j]);
        }
    }

    float* epi = EPI[wid];
    int r = lane >> 1, c0 = (lane & 1) * 8;
    #pragma unroll
    for (int i = 0; i < 2; i++)
        #pragma unroll
        for (int j = 0; j < 4; j++) {
            wmma::store_matrix_sync(epi, c[i][j], 36, wmma::mem_row_major);
            __syncwarp();
            int grow = m0 + wm * 32 + 16 * i + r;
            float w = d_bucket_w[e * NTOK + grow];
            int gcol = n0 + wn * 64 + 16 * j + c0;
            float* op = d_partial + ((size_t)e * NTOK + grow) * DDIM + gcol;
            float4 o0 = { epi[r * 36 + c0] * w,     epi[r * 36 + c0 + 1] * w,
                          epi[r * 36 + c0 + 2] * w, epi[r * 36 + c0 + 3] * w };
            float4 o1 = { epi[r * 36 + c0 + 4] * w, epi[r * 36 + c0 + 5] * w,
                          epi[r * 36 + c0 + 6] * w, epi[r * 36 + c0 + 7] * w };
            *(float4*)op = o0;
            *(float4*)(op + 4) = o1;
            __syncwarp();
        }
}

// ---------------- gather ----------------
__global__ __launch_bounds__(128) void gather_out(float* __restrict__ out) {
    int n = blockIdx.x;
    int tid = threadIdx.x;
    float acc[4] = {0.f, 0.f, 0.f, 0.f};
    #pragma unroll
    for (int e = 0; e < ENUM; e++) {
        int s = d_slot[n * ENUM + e];
        if (s >= 0) {
            const float* pp = d_partial + ((size_t)e * NTOK + s) * DDIM;
            #pragma unroll
            for (int q = 0; q < 4; q++) acc[q] += pp[tid + q * 128];
        }
    }
    #pragma unroll
    for (int q = 0; q < 4; q++) out[(size_t)n * DDIM + tid + q * 128] = acc[q];
}

// ---------------- launch ----------------
extern "C" void kernel_launch(void* const* d_in, const int* in_sizes, int n_in,
                              void* d_out, int out_size)
{
    const float* x  = (const float*)d_in[0];
    const float* Wr = (const float*)d_in[1];
    const float* br = (const float*)d_in[2];
    const float* Wg = (const float*)d_in[3];
    const float* bg = (const float*)d_in[4];
    const float* W1 = (const float*)d_in[5];
    const float* W3 = (const float*)d_in[6];
    const float* W2 = (const float*)d_in[7];
    float* out = (float*)d_out;

    routing_kernel<<<NTOK / 8, 256>>>(x, Wr, br, Wg, bg);               // 1
    build_buckets<<<ENUM, 256>>>();                                      // 2
    convw3<<<6144, 256>>>(W1, W3, W2);                                   // 3
    wmma_up<<<dim3(HDIM / 128, NTOK / 128, ENUM), 256>>>(x);            // 4 <- ncu
    wmma_down<<<dim3(DDIM / 128, NTOK / 128, ENUM), 256>>>();           // 5
    gather_out<<<NTOK, 128>>>(out);                                      // 6
}

// round 16
// speedup vs baseline: 1.8273x; 1.8273x over previous
#include <cuda_runtime.h>
#include <cuda_fp16.h>
#include <mma.h>
#include <cstdint>

using namespace nvcuda;

#define NTOK 2048
#define DDIM 512
#define HDIM 2048
#define GNUM 4
#define EPG  4
#define ENUM 16
#define GTP_THR 0.9f
#define TP_THR  0.9f
#define SCALE_W 0.5f

// ---------------- scratch ----------------
__device__ float d_tw[NTOK * ENUM];
__device__ int   d_slot[NTOK * ENUM];
__device__ int   d_bucket_tok[ENUM * NTOK];
__device__ float d_bucket_w[ENUM * NTOK];
__device__ int   d_counts[ENUM];
__device__ __half d_h16[(size_t)ENUM * NTOK * HDIM];    // 128 MB
__device__ float d_partial[(size_t)ENUM * NTOK * DDIM]; // 64 MB

// up smem: per buffer (halfs): Ah 128*40=5120, B1h 32*136=4352, B3h 4352 -> 13824
#define UP_HALFS_PER_BUF 13824
#define UP_SMEM (2 * UP_HALFS_PER_BUF * 2)   // 55296 B

// ---------------- helpers ----------------
__device__ __forceinline__ void cvthi4(float4 v, __half* hi) {
    ((__half2*)hi)[0] = __floats2half2_rn(v.x, v.y);
    ((__half2*)hi)[1] = __floats2half2_rn(v.z, v.w);
}

// ---------------- routing ----------------
__device__ __forceinline__ void top2norm(const float* logit, float thr, float* w) {
    float m = logit[0];
    #pragma unroll
    for (int i = 1; i < 4; i++) m = fmaxf(m, logit[i]);
    float p[4], s = 0.f;
    #pragma unroll
    for (int i = 0; i < 4; i++) { p[i] = expf(logit[i] - m); s += p[i]; }
    #pragma unroll
    for (int i = 0; i < 4; i++) p[i] /= s;
    int i0 = 0; float b0 = p[0];
    #pragma unroll
    for (int i = 1; i < 4; i++) if (p[i] > b0) { b0 = p[i]; i0 = i; }
    int i1 = -1; float b1 = -1.f;
    #pragma unroll
    for (int i = 0; i < 4; i++) if (i != i0 && p[i] > b1) { b1 = p[i]; i1 = i; }
    bool act1 = (b0 + b1) <= thr;
    float mp1 = act1 ? b1 : 0.f;
    float den = b0 + mp1 + 1e-9f;
    #pragma unroll
    for (int i = 0; i < 4; i++) w[i] = 0.f;
    w[i0] = b0 / den;
    w[i1] = mp1 / den;
}

__global__ __launch_bounds__(256) void routing_kernel(
    const float* __restrict__ x, const float* __restrict__ Wr,
    const float* __restrict__ br, const float* __restrict__ Wg,
    const float* __restrict__ bg)
{
    int wid = threadIdx.x >> 5, lane = threadIdx.x & 31;
    int n = blockIdx.x * 8 + wid;
    const float* xr = x + (size_t)n * DDIM;
    float xv[16];
    #pragma unroll
    for (int i = 0; i < 16; i++) xv[i] = xr[lane + 32 * i];

    float acc[20];
    #pragma unroll
    for (int g = 0; g < 4; g++) {
        float s = 0.f;
        #pragma unroll
        for (int i = 0; i < 16; i++) s += xv[i] * Wr[(lane + 32 * i) * 4 + g];
        acc[g] = s;
    }
    #pragma unroll
    for (int g = 0; g < 4; g++) {
        #pragma unroll
        for (int e = 0; e < 4; e++) {
            float s = 0.f;
            const float* wgp = Wg + (size_t)g * DDIM * EPG + e;
            #pragma unroll
            for (int i = 0; i < 16; i++) s += xv[i] * wgp[(lane + 32 * i) * 4];
            acc[4 + g * 4 + e] = s;
        }
    }
    #pragma unroll
    for (int o = 16; o; o >>= 1) {
        #pragma unroll
        for (int j = 0; j < 20; j++) acc[j] += __shfl_xor_sync(0xffffffffu, acc[j], o);
    }
    if (lane == 0) {
        float gl[4];
        #pragma unroll
        for (int g = 0; g < 4; g++) gl[g] = acc[g] + br[g];
        float wgrp[4];
        top2norm(gl, GTP_THR, wgrp);
        #pragma unroll
        for (int g = 0; g < 4; g++) {
            float el[4];
            #pragma unroll
            for (int e = 0; e < 4; e++) el[e] = acc[4 + g * 4 + e] + bg[g * 4 + e];
            float wexp[4];
            top2norm(el, TP_THR, wexp);
            #pragma unroll
            for (int e = 0; e < 4; e++) {
                d_tw[n * ENUM + g * 4 + e] = wgrp[g] * wexp[e] * SCALE_W;
                d_slot[n * ENUM + g * 4 + e] = -1;
            }
        }
    }
}

// ---------------- bucket build ----------------
__global__ __launch_bounds__(256) void build_buckets() {
    int e = blockIdx.x;
    int t = threadIdx.x;
    __shared__ int sc[256];
    int base = t * 8;
    float wv[8];
    int flags = 0, cnt = 0;
    #pragma unroll
    for (int j = 0; j < 8; j++) {
        float v = d_tw[(base + j) * ENUM + e];
        wv[j] = v;
        if (v > 0.f) { flags |= 1 << j; cnt++; }
    }
    sc[t] = cnt;
    __syncthreads();
    for (int off = 1; off < 256; off <<= 1) {
        int v = sc[t];
        int add = (t >= off) ? sc[t - off] : 0;
        __syncthreads();
        sc[t] = v + add;
        __syncthreads();
    }
    int pos = sc[t] - cnt;
    #pragma unroll
    for (int j = 0; j < 8; j++) {
        if ((flags >> j) & 1) {
            int n = base + j;
            d_bucket_tok[e * NTOK + pos] = n;
            d_bucket_w[e * NTOK + pos] = wv[j];
            d_slot[n * ENUM + e] = pos;
            pos++;
        }
    }
    if (t == 255) d_counts[e] = sc[255];
}

// no-op launch to position wmma_up in ncu's profiled slot (launch #4)
__global__ void nopk() {}

// =============================================================================
// wmma_up: block 128(M) x 128(N) for BOTH u=xW1 and v=xW3. K-chunk 32, 16 chunks.
// 8 warps (2m x 4n), warp tile 64x32 per matrix, fragments m8n32k16
// (6KB frag LDS per warp-ks vs 8KB with m16n16k16).
// Double-buffered dynamic smem, register prefetch, one sync per chunk.
// Layout per buffer (halfs): Ah[128x40]@0  B1h[32x136]@5120  B3h[32x136]@9472
// =============================================================================
__global__ __launch_bounds__(256, 1) void wmma_up(
    const float* __restrict__ x, const float* __restrict__ W1,
    const float* __restrict__ W3)
{
    extern __shared__ __align__(16) __half SMU[];
    int e = blockIdx.z;
    int cnt = d_counts[e];
    if (cnt == 0) return;
    int cntp = (cnt + 127) & ~127;
    int m0 = blockIdx.y * 128;
    if (m0 >= cntp) return;
    int n0 = blockIdx.x * 128;
    int tid = threadIdx.x, lane = tid & 31, wid = tid >> 5;
    const int NK = DDIM / 32;

    int ar = tid >> 1, ap = (tid & 1) * 16;
    int gi = m0 + ar; if (gi > cnt - 1) gi = cnt - 1;
    const float* xrow = x + (size_t)d_bucket_tok[e * NTOK + gi] * DDIM;
    int kB = tid >> 3, cB = (tid & 7) * 16;
    const float* w1p = W1 + (size_t)e * DDIM * HDIM + (size_t)kB * HDIM + n0 + cB;
    const float* w3p = W3 + (size_t)e * DDIM * HDIM + (size_t)kB * HDIM + n0 + cB;

    float4 rA[4], rB1[4], rB3[4];
    auto ldreg = [&](int kc) {
        int k0 = kc * 32;
        #pragma unroll
        for (int q = 0; q < 4; q++) rA[q] = *(const float4*)(xrow + k0 + ap + q * 4);
        #pragma unroll
        for (int q = 0; q < 4; q++) {
            rB1[q] = *(const float4*)(w1p + (size_t)k0 * HDIM + q * 4);
            rB3[q] = *(const float4*)(w3p + (size_t)k0 * HDIM + q * 4);
        }
    };
    auto sts = [&](int b) {
        __half* Ah = SMU + b * UP_HALFS_PER_BUF;
        #pragma unroll
        for (int q = 0; q < 4; q++) cvthi4(rA[q], Ah + ar * 40 + ap + q * 4);
        __half* B1h = Ah + 5120;
        __half* B3h = Ah + 9472;
        #pragma unroll
        for (int q = 0; q < 4; q++) {
            cvthi4(rB1[q], B1h + kB * 136 + cB + q * 4);
            cvthi4(rB3[q], B3h + kB * 136 + cB + q * 4);
        }
    };

    int wm = wid & 1, wn = wid >> 1;
    wmma::fragment<wmma::accumulator, 8, 32, 16, float> u[8], v[8];
    #pragma unroll
    for (int i = 0; i < 8; i++) {
        wmma::fill_fragment(u[i], 0.0f);
        wmma::fill_fragment(v[i], 0.0f);
    }

    ldreg(0);
    for (int kc = 0; kc < NK; kc++) {
        int b = kc & 1;
        sts(b);
        if (kc + 1 < NK) ldreg(kc + 1);
        __syncthreads();
        __half* Ah = SMU + b * UP_HALFS_PER_BUF;
        __half* B1h = Ah + 5120;
        __half* B3h = Ah + 9472;
        #pragma unroll
        for (int ks = 0; ks < 2; ks++) {
            wmma::fragment<wmma::matrix_a, 8, 32, 16, __half, wmma::row_major> fa[8];
            #pragma unroll
            for (int i = 0; i < 8; i++)
                wmma::load_matrix_sync(fa[i], Ah + (wm * 64 + 8 * i) * 40 + ks * 16, 40);
            wmma::fragment<wmma::matrix_b, 8, 32, 16, __half, wmma::row_major> f1, f3;
            wmma::load_matrix_sync(f1, B1h + ks * 16 * 136 + wn * 32, 136);
            wmma::load_matrix_sync(f3, B3h + ks * 16 * 136 + wn * 32, 136);
            #pragma unroll
            for (int i = 0; i < 8; i++) {
                wmma::mma_sync(u[i], fa[i], f1, u[i]);
                wmma::mma_sync(v[i], fa[i], f3, v[i]);
            }
        }
    }
    __syncthreads();

    // epilogue: h = silu(u)*v -> fp16 (accum frags of same shape share layout)
    float* epi = (float*)SMU + wid * 288;   // 8 x 36
    int r = lane >> 2, c0 = (lane & 3) * 8;
    #pragma unroll
    for (int i = 0; i < 8; i++) {
        #pragma unroll
        for (int t = 0; t < u[i].num_elements; t++) {
            float uu = u[i].x[t];
            u[i].x[t] = uu / (1.f + __expf(-uu)) * v[i].x[t];
        }
        wmma::store_matrix_sync(epi, u[i], 36, wmma::mem_row_major);
        __syncwarp();
        int grow = m0 + wm * 64 + 8 * i + r;
        int gcol = n0 + wn * 32 + c0;
        __half2* op = (__half2*)(d_h16 + ((size_t)e * NTOK + grow) * HDIM + gcol);
        #pragma unroll
        for (int q = 0; q < 4; q++)
            op[q] = __floats2half2_rn(epi[r * 36 + c0 + 2 * q],
                                      epi[r * 36 + c0 + 2 * q + 1]);
        __syncwarp();
    }
}

// =============================================================================
// wmma_down: block 128(M) x 128(N). K-chunk 32, 64 chunks. 2 CTAs/SM.
// 8 warps (4m x 2n), warp tile 32x64, fragments m8n32k16 (5KB frag LDS per
// warp-ks vs 6KB), single live fb to fit 128 regs.
// Static smem per buffer (halfs): Ah[128x40]@0  Bh[32x136]@5120  (9472)
// =============================================================================
__global__ __launch_bounds__(256, 2) void wmma_down(const float* __restrict__ W2)
{
    __shared__ __align__(16) __half SM[2][9472];   // 37888 B
    int e = blockIdx.z;
    int cnt = d_counts[e];
    if (cnt == 0) return;
    int cntp = (cnt + 127) & ~127;
    int m0 = blockIdx.y * 128;
    if (m0 >= cntp) return;
    int n0 = blockIdx.x * 128;
    int tid = threadIdx.x, lane = tid & 31, wid = tid >> 5;
    const int NK = HDIM / 32;

    int ar = tid >> 1, ap = (tid & 1) * 16;
    const __half* arow = d_h16 + ((size_t)e * NTOK + m0 + ar) * HDIM;
    int kB = tid >> 3, cB = (tid & 7) * 16;
    const float* w2p = W2 + (size_t)e * HDIM * DDIM + (size_t)kB * DDIM + n0 + cB;

    uint4 rA[2];
    float4 rB[4];
    auto ldreg = [&](int kc) {
        int k0 = kc * 32;
        rA[0] = *(const uint4*)(arow + k0 + ap);
        rA[1] = *(const uint4*)(arow + k0 + ap + 8);
        #pragma unroll
        for (int q = 0; q < 4; q++)
            rB[q] = *(const float4*)(w2p + (size_t)k0 * DDIM + q * 4);
    };
    auto sts = [&](int b) {
        __half* Ah = SM[b];
        *(uint4*)(Ah + ar * 40 + ap) = rA[0];
        *(uint4*)(Ah + ar * 40 + ap + 8) = rA[1];
        __half* Bh = SM[b] + 5120;
        #pragma unroll
        for (int q = 0; q < 4; q++)
            cvthi4(rB[q], Bh + kB * 136 + cB + q * 4);
    };

    int wm = wid & 3, wn = wid >> 2;
    wmma::fragment<wmma::accumulator, 8, 32, 16, float> c[4][2];
    #pragma unroll
    for (int i = 0; i < 4; i++)
        #pragma unroll
        for (int j = 0; j < 2; j++) wmma::fill_fragment(c[i][j], 0.0f);

    ldreg(0);
    for (int kc = 0; kc < NK; kc++) {
        int b = kc & 1;
        sts(b);
        if (kc + 1 < NK) ldreg(kc + 1);
        __syncthreads();
        __half* Ah = SM[b];
        __half* Bh = SM[b] + 5120;
        #pragma unroll
        for (int ks = 0; ks < 2; ks++) {
            wmma::fragment<wmma::matrix_a, 8, 32, 16, __half, wmma::row_major> fa[4];
            #pragma unroll
            for (int i = 0; i < 4; i++)
                wmma::load_matrix_sync(fa[i], Ah + (wm * 32 + 8 * i) * 40 + ks * 16, 40);
            #pragma unroll
            for (int j = 0; j < 2; j++) {
                wmma::fragment<wmma::matrix_b, 8, 32, 16, __half, wmma::row_major> fb;
                wmma::load_matrix_sync(fb, Bh + ks * 16 * 136 + wn * 64 + 32 * j, 136);
                #pragma unroll
                for (int i = 0; i < 4; i++)
                    wmma::mma_sync(c[i][j], fa[i], fb, c[i][j]);
            }
        }
    }
    __syncthreads();

    float* epi = (float*)SM + wid * 288;   // 8 x 36
    int r = lane >> 2, c0 = (lane & 3) * 8;
    #pragma unroll
    for (int i = 0; i < 4; i++)
        #pragma unroll
        for (int j = 0; j < 2; j++) {
            wmma::store_matrix_sync(epi, c[i][j], 36, wmma::mem_row_major);
            __syncwarp();
            int grow = m0 + wm * 32 + 8 * i + r;
            float w = d_bucket_w[e * NTOK + grow];
            int gcol = n0 + wn * 64 + 32 * j + c0;
            float* op = d_partial + ((size_t)e * NTOK + grow) * DDIM + gcol;
            float4 o0 = { epi[r * 36 + c0] * w,     epi[r * 36 + c0 + 1] * w,
                          epi[r * 36 + c0 + 2] * w, epi[r * 36 + c0 + 3] * w };
            float4 o1 = { epi[r * 36 + c0 + 4] * w, epi[r * 36 + c0 + 5] * w,
                          epi[r * 36 + c0 + 6] * w, epi[r * 36 + c0 + 7] * w };
            *(float4*)op = o0;
            *(float4*)(op + 4) = o1;
            __syncwarp();
        }
}

// ---------------- gather ----------------
__global__ __launch_bounds__(128) void gather_out(float* __restrict__ out) {
    int n = blockIdx.x;
    int tid = threadIdx.x;
    float acc[4] = {0.f, 0.f, 0.f, 0.f};
    #pragma unroll
    for (int e = 0; e < ENUM; e++) {
        int s = d_slot[n * ENUM + e];
        if (s >= 0) {
            const float* pp = d_partial + ((size_t)e * NTOK + s) * DDIM;
            #pragma unroll
            for (int q = 0; q < 4; q++) acc[q] += pp[tid + q * 128];
        }
    }
    #pragma unroll
    for (int q = 0; q < 4; q++) out[(size_t)n * DDIM + tid + q * 128] = acc[q];
}

// ---------------- launch ----------------
extern "C" void kernel_launch(void* const* d_in, const int* in_sizes, int n_in,
                              void* d_out, int out_size)
{
    const float* x  = (const float*)d_in[0];
    const float* Wr = (const float*)d_in[1];
    const float* br = (const float*)d_in[2];
    const float* Wg = (const float*)d_in[3];
    const float* bg = (const float*)d_in[4];
    const float* W1 = (const float*)d_in[5];
    const float* W3 = (const float*)d_in[6];
    const float* W2 = (const float*)d_in[7];
    float* out = (float*)d_out;

    cudaFuncSetAttribute(wmma_up, cudaFuncAttributeMaxDynamicSharedMemorySize, UP_SMEM);

    routing_kernel<<<NTOK / 8, 256>>>(x, Wr, br, Wg, bg);                        // 1
    build_buckets<<<ENUM, 256>>>();                                               // 2
    nopk<<<1, 32>>>();                                                            // 3
    wmma_up<<<dim3(HDIM / 128, NTOK / 128, ENUM), 256, UP_SMEM>>>(x, W1, W3);    // 4 <- ncu
    wmma_down<<<dim3(DDIM / 128, NTOK / 128, ENUM), 256>>>(W2);                  // 5
    gather_out<<<NTOK, 128>>>(out);                                               // 6
}